// round 1
// baseline (speedup 1.0000x reference)
#include <cuda_runtime.h>
#include <cstdint>

// Problem constants
#define BB   8
#define NN   8192
#define MM   2000
#define KK   16
#define C1W  128
#define C2W  256
#define NOUT 100

// ---------------- scratch (device globals; no allocations allowed) ----------
__device__ float  g_sub [BB * MM * 3];     // FPS-subsampled coords
__device__ int    g_idx1[BB * MM * KK];    // knn over raw points
__device__ int    g_idx2[BB * MM * KK];    // knn over sub points
__device__ float  g_f1  [BB * MM * C1W];   // layer-1 features
__device__ float  g_f2  [BB * MM * C2W];   // layer-2 features
__device__ float4 g_W2q [33 * C2W];        // W2 reordered: [fq][c] quads, feature order = [f1(128), rel(3), pad0]

// ---------------- W2 prep: reorder + transpose to quad-major ----------------
// feature reorder: feat'[0..127] = fg (orig W2 rows 3..130), feat'[128..130] = rel (rows 0..2), feat'[131] = 0
__global__ void w2prep_kernel(const float* __restrict__ W2) {
    int t = blockIdx.x * 256 + threadIdx.x;
    if (t >= 33 * C2W) return;
    int fq = t >> 8, c = t & 255;
    float v[4];
#pragma unroll
    for (int e = 0; e < 4; e++) {
        int fp = fq * 4 + e;
        float val = 0.f;
        if (fp < 131) {
            int r = (fp < 128) ? (fp + 3) : (fp - 128);
            val = W2[r * C2W + c];
        }
        v[e] = val;
    }
    g_W2q[t] = make_float4(v[0], v[1], v[2], v[3]);
}

// ---------------- FPS: 1 block per batch, all points in registers ----------
__global__ void __launch_bounds__(1024, 1) fps_kernel(const float* __restrict__ x) {
    const int b = blockIdx.x;
    const float* xb = x + (size_t)b * NN * 3;
    const int t = threadIdx.x;

    float px[8], py[8], pz[8], mind[8];
#pragma unroll
    for (int j = 0; j < 8; j++) {
        int i = t + j * 1024;
        px[j] = xb[3 * i]; py[j] = xb[3 * i + 1]; pz[j] = xb[3 * i + 2];
        mind[j] = 1e30f;
    }

    __shared__ float s_val[2][32];
    __shared__ int   s_idx[2][32];

    if (t == 0) {
        float* sp = g_sub + (size_t)(b * MM) * 3;
        sp[0] = xb[0]; sp[1] = xb[1]; sp[2] = xb[2];
    }
    float cx = xb[0], cy = xb[1], cz = xb[2];

    for (int step = 1; step < MM; step++) {
        // update min-dist + local argmax (first-index ties kept: j ascending => i ascending)
        float bv = -1.0f; int bix = 0;
#pragma unroll
        for (int j = 0; j < 8; j++) {
            float dx = px[j] - cx, dy = py[j] - cy, dz = pz[j] - cz;
            float d = dx * dx + dy * dy + dz * dz;
            float mj = fminf(mind[j], d);
            mind[j] = mj;
            if (mj > bv) { bv = mj; bix = t + j * 1024; }
        }
        // warp butterfly reduce (max val, min idx on tie)
#pragma unroll
        for (int o = 16; o; o >>= 1) {
            float ov = __shfl_xor_sync(0xffffffffu, bv, o);
            int   oi = __shfl_xor_sync(0xffffffffu, bix, o);
            if (ov > bv || (ov == bv && oi < bix)) { bv = ov; bix = oi; }
        }
        int buf = step & 1;
        if ((t & 31) == 0) { s_val[buf][t >> 5] = bv; s_idx[buf][t >> 5] = bix; }
        __syncthreads();
        // every warp redundantly reduces the 32 warp winners -> all threads know result, no 2nd bar
        {
            int lane = t & 31;
            bv = s_val[buf][lane]; bix = s_idx[buf][lane];
#pragma unroll
            for (int o = 16; o; o >>= 1) {
                float ov = __shfl_xor_sync(0xffffffffu, bv, o);
                int   oi = __shfl_xor_sync(0xffffffffu, bix, o);
                if (ov > bv || (ov == bv && oi < bix)) { bv = ov; bix = oi; }
            }
        }
        cx = xb[3 * bix]; cy = xb[3 * bix + 1]; cz = xb[3 * bix + 2]; // broadcast LDG, L1-resident
        if (t == 0) {
            float* sp = g_sub + (size_t)(b * MM + step) * 3;
            sp[0] = cx; sp[1] = cy; sp[2] = cz;
        }
    }
}

// ---------------- KNN: per-thread query, sorted top-16 in registers --------
#define KTS 2048
__device__ __forceinline__ void knn_body(const float* __restrict__ src, int nsrc,
                                         int* __restrict__ outidx) {
    __shared__ float4 s_tile[KTS];
    int b = blockIdx.y;
    int m = blockIdx.x * blockDim.x + threadIdx.x;

    float qx = 0, qy = 0, qz = 0, qq = 0;
    if (m < MM) {
        const float* qp = g_sub + (size_t)(b * MM + m) * 3;
        qx = qp[0]; qy = qp[1]; qz = qp[2];
        qq = qx * qx + qy * qy + qz * qz;
    }
    float dist[KK]; int idxr[KK];
#pragma unroll
    for (int j = 0; j < KK; j++) { dist[j] = 1e38f; idxr[j] = 0; }

    for (int base = 0; base < nsrc; base += KTS) {
        int cnt = min(KTS, nsrc - base);
        __syncthreads();
        for (int i = threadIdx.x; i < cnt; i += blockDim.x) {
            const float* sp = src + (size_t)(b * nsrc + base + i) * 3;
            float sx = sp[0], sy = sp[1], sz = sp[2];
            s_tile[i] = make_float4(sx, sy, sz, sx * sx + sy * sy + sz * sz);
        }
        __syncthreads();
        if (m < MM) {
            for (int i = 0; i < cnt; i++) {
                float4 s = s_tile[i];
                float d2 = (qq + s.w) - 2.0f * (qx * s.x + qy * s.y + qz * s.z);
                if (d2 < dist[KK - 1]) {              // strict < : stable (lower-index) ties, matches top_k
                    dist[KK - 1] = d2; idxr[KK - 1] = base + i;
#pragma unroll
                    for (int j = KK - 1; j > 0; --j) {
                        if (dist[j] < dist[j - 1]) {
                            float td = dist[j]; dist[j] = dist[j - 1]; dist[j - 1] = td;
                            int ti = idxr[j]; idxr[j] = idxr[j - 1]; idxr[j - 1] = ti;
                        }
                    }
                }
            }
        }
    }
    if (m < MM) {
        int* op = outidx + (size_t)(b * MM + m) * KK;
#pragma unroll
        for (int j = 0; j < KK; j++) op[j] = idxr[j];
    }
}

__global__ void __launch_bounds__(128) knn1_kernel(const float* __restrict__ x) {
    knn_body(x, NN, g_idx1);
}
__global__ void __launch_bounds__(128) knn2_kernel() {
    knn_body(g_sub, MM, g_idx2);
}

// ---------------- Layer 1: warp per query, 4 channels per lane -------------
__global__ void __launch_bounds__(128) layer1_kernel(const float* __restrict__ x,
                                                     const float* __restrict__ W1,
                                                     const float* __restrict__ b1) {
    __shared__ float sW[6 * C1W];
    int tid = threadIdx.x;
    for (int i = tid; i < 6 * C1W; i += 128) sW[i] = W1[i];
    __syncthreads();

    int warp = tid >> 5, lane = tid & 31;
    int b = blockIdx.y;
    int m = blockIdx.x * 4 + warp;

    const float* cp = g_sub + (size_t)(b * MM + m) * 3;
    float cx = cp[0], cy = cp[1], cz = cp[2];
    int c0 = lane * 4;
    float bb[4] = { b1[c0], b1[c0 + 1], b1[c0 + 2], b1[c0 + 3] };
    float best[4] = { 0.f, 0.f, 0.f, 0.f };
    const int* ip = g_idx1 + (size_t)(b * MM + m) * KK;

#pragma unroll 1
    for (int k = 0; k < KK; k++) {
        int n = ip[k];
        const float* np = x + ((size_t)b * NN + n) * 3;
        float nx = np[0], ny = np[1], nz = np[2];
        float f[6]; f[0] = nx - cx; f[1] = ny - cy; f[2] = nz - cz; f[3] = nx; f[4] = ny; f[5] = nz;
        float a[4] = { bb[0], bb[1], bb[2], bb[3] };
#pragma unroll
        for (int ff = 0; ff < 6; ff++) {
            const float* w = sW + ff * C1W + c0;
            a[0] += f[ff] * w[0]; a[1] += f[ff] * w[1];
            a[2] += f[ff] * w[2]; a[3] += f[ff] * w[3];
        }
#pragma unroll
        for (int e = 0; e < 4; e++) best[e] = fmaxf(best[e], fmaxf(a[e], 0.f));
    }
    *(float4*)(g_f1 + ((size_t)(b * MM + m) * C1W + c0)) =
        make_float4(best[0], best[1], best[2], best[3]);
}

// ---------------- Layer 2: 256 threads = channels, 4 queries per block -----
#define CH 4
__global__ void __launch_bounds__(256, 1) layer2_kernel(const float* __restrict__ b2) {
    __shared__ float sfeat[CH * 16 * 132];  // [pair][132], f1 part at [0..127] (float4 aligned), rel at [128..130], pad
    __shared__ int   s_n[CH * 16];

    int b = blockIdx.y, m0 = blockIdx.x * CH;
    int tid = threadIdx.x;

    // Step A: indices + rel features
    if (tid < CH * 16) {
        int mm = tid >> 4, k = tid & 15;
        int m = m0 + mm;
        int n = g_idx2[(size_t)(b * MM + m) * KK + k];
        s_n[tid] = n;
        const float* cp = g_sub + (size_t)(b * MM + m) * 3;
        const float* np = g_sub + (size_t)(b * MM + n) * 3;
        float* row = sfeat + tid * 132;
        row[128] = np[0] - cp[0];
        row[129] = np[1] - cp[1];
        row[130] = np[2] - cp[2];
        row[131] = 0.f;
    }
    __syncthreads();
    // Step B: gather f1 rows (float4)
    for (int t = tid; t < CH * 16 * 32; t += 256) {
        int p = t >> 5, fq = t & 31;
        int n = s_n[p];
        float4 v = *(const float4*)(g_f1 + (size_t)(b * MM + n) * C1W + fq * 4);
        *(float4*)(sfeat + p * 132 + fq * 4) = v;
    }
    // cache this channel's W2 column in registers (33 quads = 132 regs)
    int c = tid;
    float4 wreg[33];
#pragma unroll
    for (int q = 0; q < 33; q++) wreg[q] = g_W2q[q * C2W + c];
    float bc = b2[c];
    __syncthreads();

    float best[CH];
#pragma unroll
    for (int mm = 0; mm < CH; mm++) best[mm] = 0.f;

#pragma unroll 1
    for (int k = 0; k < 16; k++) {
        float acc[CH];
#pragma unroll
        for (int mm = 0; mm < CH; mm++) acc[mm] = bc;
#pragma unroll
        for (int q = 0; q < 33; q++) {
            float4 w = wreg[q];
#pragma unroll
            for (int mm = 0; mm < CH; mm++) {
                float4 v = *(const float4*)(sfeat + (mm * 16 + k) * 132 + q * 4);
                acc[mm] += v.x * w.x;
                acc[mm] += v.y * w.y;
                acc[mm] += v.z * w.z;
                acc[mm] += v.w * w.w;
            }
        }
#pragma unroll
        for (int mm = 0; mm < CH; mm++)
            best[mm] = fmaxf(best[mm], fmaxf(acc[mm], 0.f));
    }
#pragma unroll
    for (int mm = 0; mm < CH; mm++)
        g_f2[(size_t)(b * MM + m0 + mm) * C2W + c] = best[mm];
}

// ---------------- fused adaptive max+avg pool ------------------------------
__global__ void __launch_bounds__(256) pool_kernel(float* __restrict__ out) {
    int c = threadIdx.x;
    int o = blockIdx.x;
    int b = blockIdx.y;
    const float* f = g_f2 + ((size_t)(b * MM + o * 20) * C2W) + c;
    float mx = -1e38f, sm = 0.f;
#pragma unroll
    for (int w = 0; w < 20; w++) {
        float v = f[(size_t)w * C2W];
        mx = fmaxf(mx, v);
        sm += v;
    }
    out[((size_t)b * C2W + c) * NOUT + o] = mx + sm / 20.0f;
}

// ---------------- launch ----------------------------------------------------
extern "C" void kernel_launch(void* const* d_in, const int* in_sizes, int n_in,
                              void* d_out, int out_size) {
    const float* x  = (const float*)d_in[0];
    const float* W1 = (const float*)d_in[1];
    const float* b1 = (const float*)d_in[2];
    const float* W2 = (const float*)d_in[3];
    const float* b2 = (const float*)d_in[4];
    float* out = (float*)d_out;

    w2prep_kernel<<<33, 256>>>(W2);
    fps_kernel<<<BB, 1024>>>(x);
    knn1_kernel<<<dim3((MM + 127) / 128, BB), 128>>>(x);
    knn2_kernel<<<dim3((MM + 127) / 128, BB), 128>>>();
    layer1_kernel<<<dim3(MM / 4, BB), 128>>>(x, W1, b1);
    layer2_kernel<<<dim3(MM / CH, BB), 256>>>(b2);
    pool_kernel<<<dim3(NOUT, BB), 256>>>(out);
}

// round 2
// speedup vs baseline: 1.1417x; 1.1417x over previous
#include <cuda_runtime.h>
#include <cstdint>

typedef unsigned long long u64;

// Problem constants
#define BB   8
#define NN   8192
#define MM   2000
#define KK   16
#define C1W  128
#define C2W  256
#define NOUT 100

// ---------------- scratch (device globals; no allocations allowed) ----------
__device__ float  g_sub [BB * MM * 3];     // FPS-subsampled coords
__device__ int    g_idx1[BB * MM * KK];    // knn over raw points
__device__ int    g_idx2[BB * MM * KK];    // knn over sub points
__device__ float  g_f1  [BB * MM * C1W];   // layer-1 features
__device__ float  g_f2  [BB * MM * C2W];   // layer-2 features
__device__ float4 g_W2q [33 * C2W];        // W2 reordered: [fq][c] quads, feat order = [f1(128), rel(3), pad0]

__device__ __forceinline__ u64 ffma2(u64 a, u64 b, u64 c) {
    u64 d;
    asm("fma.rn.f32x2 %0, %1, %2, %3;" : "=l"(d) : "l"(a), "l"(b), "l"(c));
    return d;
}
__device__ __forceinline__ u64 umax64(u64 a, u64 b) { return a > b ? a : b; }

// ---------------- W2 prep: reorder + transpose to quad-major ----------------
__global__ void w2prep_kernel(const float* __restrict__ W2) {
    int t = blockIdx.x * 256 + threadIdx.x;
    if (t >= 33 * C2W) return;
    int fq = t >> 8, c = t & 255;
    float v[4];
#pragma unroll
    for (int e = 0; e < 4; e++) {
        int fp = fq * 4 + e;
        float val = 0.f;
        if (fp < 131) {
            int r = (fp < 128) ? (fp + 3) : (fp - 128);
            val = W2[r * C2W + c];
        }
        v[e] = val;
    }
    g_W2q[t] = make_float4(v[0], v[1], v[2], v[3]);
}

// ---------------- FPS: 1 block per batch, points in registers, u64 keys ----
__global__ void __launch_bounds__(1024, 1) fps_kernel(const float* __restrict__ x) {
    const int b = blockIdx.x;
    const float* xb = x + (size_t)b * NN * 3;
    const int t = threadIdx.x;

    float px[8], py[8], pz[8], mind[8];
#pragma unroll
    for (int j = 0; j < 8; j++) {
        int i = t + j * 1024;
        px[j] = xb[3 * i]; py[j] = xb[3 * i + 1]; pz[j] = xb[3 * i + 2];
        mind[j] = 1e30f;
    }

    __shared__ u64 s_key[2][32];

    if (t == 0) {
        float* sp = g_sub + (size_t)(b * MM) * 3;
        sp[0] = xb[0]; sp[1] = xb[1]; sp[2] = xb[2];
    }
    float cx = xb[0], cy = xb[1], cz = xb[2];

    for (int step = 1; step < MM; step++) {
        // update min-dist + packed argmax key (val bits high, ~idx low: max => max val, min idx on tie)
        u64 bk = 0;
#pragma unroll
        for (int j = 0; j < 8; j++) {
            float dx = px[j] - cx, dy = py[j] - cy, dz = pz[j] - cz;
            float d = dx * dx + dy * dy + dz * dz;
            float mj = fminf(mind[j], d);
            mind[j] = mj;
            u64 key = ((u64)__float_as_uint(mj) << 32) | (unsigned)(~(t + j * 1024));
            bk = umax64(bk, key);
        }
#pragma unroll
        for (int o = 16; o; o >>= 1)
            bk = umax64(bk, __shfl_xor_sync(0xffffffffu, bk, o));
        int buf = step & 1;
        if ((t & 31) == 0) s_key[buf][t >> 5] = bk;
        __syncthreads();
        {
            bk = s_key[buf][t & 31];
#pragma unroll
            for (int o = 16; o; o >>= 1)
                bk = umax64(bk, __shfl_xor_sync(0xffffffffu, bk, o));
        }
        int bix = (int)(~(unsigned)(bk & 0xffffffffu));
        cx = xb[3 * bix]; cy = xb[3 * bix + 1]; cz = xb[3 * bix + 2]; // broadcast LDG, L1-resident
        if (t == 0) {
            float* sp = g_sub + (size_t)(b * MM + step) * 3;
            sp[0] = cx; sp[1] = cy; sp[2] = cz;
        }
    }
}

// ---------------- KNN: 8-way interleaved candidate split per query ----------
// Block = 256 threads = 32 queries x 8 splits. Split s owns candidates i%8==s.
// Each sub-thread keeps a sorted top-16; in-block 8-way merge with exact
// (dist, idx) tie-break reproduces global stable top-16.
#define KTS 2048
__device__ __forceinline__ void knn_split_body(const float* __restrict__ src, int nsrc,
                                               int* __restrict__ outidx) {
    __shared__ __align__(16) float4 s_tile[KTS];   // 32KB; reused as merge buffer
    const int tid = threadIdx.x;
    const int q = tid >> 3, s = tid & 7;
    const int b = blockIdx.y;
    const int m = blockIdx.x * 32 + q;
    const bool valid = (m < MM);

    float qx = 0.f, qy = 0.f, qz = 0.f, qq = 0.f;
    if (valid) {
        const float* qp = g_sub + (size_t)(b * MM + m) * 3;
        qx = qp[0]; qy = qp[1]; qz = qp[2];
        qq = qx * qx + qy * qy + qz * qz;
    }
    float dist[KK]; int idxr[KK];
#pragma unroll
    for (int j = 0; j < KK; j++) { dist[j] = 1e38f; idxr[j] = 0; }

    for (int base = 0; base < nsrc; base += KTS) {
        const int cnt = min(KTS, nsrc - base);
        for (int i = tid; i < cnt; i += 256) {
            const float* sp = src + (size_t)(b * nsrc + base + i) * 3;
            float sx = sp[0], sy = sp[1], sz = sp[2];
            s_tile[i] = make_float4(sx, sy, sz, sx * sx + sy * sy + sz * sz);
        }
        __syncthreads();
        if (valid) {
            if (cnt == KTS) {
#pragma unroll 4
                for (int j = s; j < KTS; j += 8) {
                    float4 sv = s_tile[j];
                    float d2 = (qq + sv.w) - 2.0f * (qx * sv.x + qy * sv.y + qz * sv.z);
                    if (d2 < dist[KK - 1]) {
                        dist[KK - 1] = d2; idxr[KK - 1] = base + j;
#pragma unroll
                        for (int r = KK - 1; r > 0; --r) {
                            if (dist[r] < dist[r - 1]) {
                                float td = dist[r]; dist[r] = dist[r - 1]; dist[r - 1] = td;
                                int ti = idxr[r]; idxr[r] = idxr[r - 1]; idxr[r - 1] = ti;
                            }
                        }
                    }
                }
            } else {
                for (int j = s; j < cnt; j += 8) {
                    float4 sv = s_tile[j];
                    float d2 = (qq + sv.w) - 2.0f * (qx * sv.x + qy * sv.y + qz * sv.z);
                    if (d2 < dist[KK - 1]) {
                        dist[KK - 1] = d2; idxr[KK - 1] = base + j;
#pragma unroll
                        for (int r = KK - 1; r > 0; --r) {
                            if (dist[r] < dist[r - 1]) {
                                float td = dist[r]; dist[r] = dist[r - 1]; dist[r - 1] = td;
                                int ti = idxr[r]; idxr[r] = idxr[r - 1]; idxr[r - 1] = ti;
                            }
                        }
                    }
                }
            }
        }
        __syncthreads();   // protects tile for next load AND lists before merge reuse
    }

    // ---- merge: smem layout [r][256] conflict-free writes ----
    float* md = (float*)s_tile;              // 16KB: 16*256 floats
    int*   mi = (int*)s_tile + 4096;         // next 16KB
#pragma unroll
    for (int r = 0; r < KK; r++) {
        md[r * 256 + tid] = dist[r];
        mi[r * 256 + tid] = idxr[r];
    }
    __syncthreads();

    if (tid < 32) {
        int mq = blockIdx.x * 32 + tid;
        if (mq < MM) {
            int p[8] = {0, 0, 0, 0, 0, 0, 0, 0};
            int* op = outidx + (size_t)(b * MM + mq) * KK;
#pragma unroll 1
            for (int r = 0; r < KK; r++) {
                float bd = 3e38f; int bi = 0x7fffffff; int bs = 0;
#pragma unroll
                for (int ss = 0; ss < 8; ss++) {
                    int ps = p[ss];
                    if (ps < KK) {
                        float d = md[ps * 256 + tid * 8 + ss];
                        int   ii = mi[ps * 256 + tid * 8 + ss];
                        if (d < bd || (d == bd && ii < bi)) { bd = d; bi = ii; bs = ss; }
                    }
                }
                p[bs]++;
                op[r] = bi;
            }
        }
    }
}

__global__ void __launch_bounds__(256) knn1_kernel(const float* __restrict__ x) {
    knn_split_body(x, NN, g_idx1);
}
__global__ void __launch_bounds__(256) knn2_kernel() {
    knn_split_body(g_sub, MM, g_idx2);
}

// ---------------- Layer 1: warp per query, 4 channels per lane -------------
__global__ void __launch_bounds__(128) layer1_kernel(const float* __restrict__ x,
                                                     const float* __restrict__ W1,
                                                     const float* __restrict__ b1) {
    __shared__ float sW[6 * C1W];
    int tid = threadIdx.x;
    for (int i = tid; i < 6 * C1W; i += 128) sW[i] = W1[i];
    __syncthreads();

    int warp = tid >> 5, lane = tid & 31;
    int b = blockIdx.y;
    int m = blockIdx.x * 4 + warp;

    const float* cp = g_sub + (size_t)(b * MM + m) * 3;
    float cx = cp[0], cy = cp[1], cz = cp[2];
    int c0 = lane * 4;
    float bb[4] = { b1[c0], b1[c0 + 1], b1[c0 + 2], b1[c0 + 3] };
    float best[4] = { 0.f, 0.f, 0.f, 0.f };
    const int* ip = g_idx1 + (size_t)(b * MM + m) * KK;

#pragma unroll 1
    for (int k = 0; k < KK; k++) {
        int n = ip[k];
        const float* np = x + ((size_t)b * NN + n) * 3;
        float nx = np[0], ny = np[1], nz = np[2];
        float f[6]; f[0] = nx - cx; f[1] = ny - cy; f[2] = nz - cz; f[3] = nx; f[4] = ny; f[5] = nz;
        float a[4] = { bb[0], bb[1], bb[2], bb[3] };
#pragma unroll
        for (int ff = 0; ff < 6; ff++) {
            const float* w = sW + ff * C1W + c0;
            a[0] += f[ff] * w[0]; a[1] += f[ff] * w[1];
            a[2] += f[ff] * w[2]; a[3] += f[ff] * w[3];
        }
#pragma unroll
        for (int e = 0; e < 4; e++) best[e] = fmaxf(best[e], fmaxf(a[e], 0.f));
    }
    *(float4*)(g_f1 + ((size_t)(b * MM + m) * C1W + c0)) =
        make_float4(best[0], best[1], best[2], best[3]);
}

// ---------------- Layer 2: 256 threads = channels, 4 queries, FFMA2 --------
#define CH 4
__global__ void __launch_bounds__(256, 1) layer2_kernel(const float* __restrict__ b2) {
    __shared__ __align__(16) float sfeat[CH * 16 * 132];  // [pair][132]: f1 at [0..127], rel [128..130], pad
    __shared__ int s_n[CH * 16];

    int b = blockIdx.y, m0 = blockIdx.x * CH;
    int tid = threadIdx.x;

    // Step A: indices + rel features
    if (tid < CH * 16) {
        int mm = tid >> 4, k = tid & 15;
        int m = m0 + mm;
        int n = g_idx2[(size_t)(b * MM + m) * KK + k];
        s_n[tid] = n;
        const float* cp = g_sub + (size_t)(b * MM + m) * 3;
        const float* np = g_sub + (size_t)(b * MM + n) * 3;
        float* row = sfeat + tid * 132;
        row[128] = np[0] - cp[0];
        row[129] = np[1] - cp[1];
        row[130] = np[2] - cp[2];
        row[131] = 0.f;
    }
    __syncthreads();
    // Step B: gather f1 rows (float4)
    for (int t = tid; t < CH * 16 * 32; t += 256) {
        int p = t >> 5, fq = t & 31;
        int n = s_n[p];
        float4 v = *(const float4*)(g_f1 + (size_t)(b * MM + n) * C1W + fq * 4);
        *(float4*)(sfeat + p * 132 + fq * 4) = v;
    }
    // W2 column for this channel, packed into 66 f32x2 pairs (132 regs)
    int c = tid;
    u64 wpk[66];
#pragma unroll
    for (int qd = 0; qd < 33; qd++) {
        float4 w = g_W2q[qd * C2W + c];
        wpk[2 * qd]     = ((u64)__float_as_uint(w.y) << 32) | __float_as_uint(w.x);
        wpk[2 * qd + 1] = ((u64)__float_as_uint(w.w) << 32) | __float_as_uint(w.z);
    }
    u64 bias = (u64)__float_as_uint(b2[c]);   // lo = bias, hi = 0
    __syncthreads();

    float best[CH];
#pragma unroll
    for (int mm = 0; mm < CH; mm++) best[mm] = 0.f;

#pragma unroll 1
    for (int k = 0; k < 16; k++) {
        u64 acc[CH];
#pragma unroll
        for (int mm = 0; mm < CH; mm++) acc[mm] = bias;
#pragma unroll
        for (int q2 = 0; q2 < 33; q2++) {
#pragma unroll
            for (int mm = 0; mm < CH; mm++) {
                const ulonglong2* vrow = (const ulonglong2*)(sfeat + (mm * 16 + k) * 132);
                ulonglong2 v = vrow[q2];
                acc[mm] = ffma2(v.x, wpk[2 * q2], acc[mm]);
                acc[mm] = ffma2(v.y, wpk[2 * q2 + 1], acc[mm]);
            }
        }
#pragma unroll
        for (int mm = 0; mm < CH; mm++) {
            float lo = __uint_as_float((unsigned)(acc[mm] & 0xffffffffu));
            float hi = __uint_as_float((unsigned)(acc[mm] >> 32));
            float a = lo + hi;
            best[mm] = fmaxf(best[mm], fmaxf(a, 0.f));
        }
    }
#pragma unroll
    for (int mm = 0; mm < CH; mm++)
        g_f2[(size_t)(b * MM + m0 + mm) * C2W + c] = best[mm];
}

// ---------------- fused adaptive max+avg pool ------------------------------
__global__ void __launch_bounds__(256) pool_kernel(float* __restrict__ out) {
    int c = threadIdx.x;
    int o = blockIdx.x;
    int b = blockIdx.y;
    const float* f = g_f2 + ((size_t)(b * MM + o * 20) * C2W) + c;
    float mx = -1e38f, sm = 0.f;
#pragma unroll
    for (int w = 0; w < 20; w++) {
        float v = f[(size_t)w * C2W];
        mx = fmaxf(mx, v);
        sm += v;
    }
    out[((size_t)b * C2W + c) * NOUT + o] = mx + sm / 20.0f;
}

// ---------------- launch ----------------------------------------------------
extern "C" void kernel_launch(void* const* d_in, const int* in_sizes, int n_in,
                              void* d_out, int out_size) {
    const float* x  = (const float*)d_in[0];
    const float* W1 = (const float*)d_in[1];
    const float* b1 = (const float*)d_in[2];
    const float* W2 = (const float*)d_in[3];
    const float* b2 = (const float*)d_in[4];
    float* out = (float*)d_out;

    w2prep_kernel<<<33, 256>>>(W2);
    fps_kernel<<<BB, 1024>>>(x);
    knn1_kernel<<<dim3((MM + 31) / 32, BB), 256>>>(x);
    knn2_kernel<<<dim3((MM + 31) / 32, BB), 256>>>();
    layer1_kernel<<<dim3(MM / 4, BB), 128>>>(x, W1, b1);
    layer2_kernel<<<dim3(MM / CH, BB), 256>>>(b2);
    pool_kernel<<<dim3(NOUT, BB), 256>>>(out);
}

// round 3
// speedup vs baseline: 1.3870x; 1.2149x over previous
#include <cuda_runtime.h>
#include <cstdint>

typedef unsigned long long u64;

// Problem constants
#define BB   8
#define NN   8192
#define MM   2000
#define KK   16
#define C1W  128
#define C2W  256
#define NOUT 100

// ---------------- scratch (device globals; no allocations allowed) ----------
__device__ float  g_sub [BB * MM * 3];     // FPS-subsampled coords
__device__ int    g_idx1[BB * MM * KK];    // knn over raw points
__device__ int    g_idx2[BB * MM * KK];    // knn over sub points
__device__ float  g_f1  [BB * MM * C1W];   // layer-1 features
__device__ float  g_f2  [BB * MM * C2W];   // layer-2 features
__device__ float4 g_W2q [33 * C2W];        // W2 reordered: [fq][c] quads

__device__ __forceinline__ u64 ffma2(u64 a, u64 b, u64 c) {
    u64 d;
    asm("fma.rn.f32x2 %0, %1, %2, %3;" : "=l"(d) : "l"(a), "l"(b), "l"(c));
    return d;
}
__device__ __forceinline__ unsigned redux_max_u32(unsigned v) {
    unsigned r;
    asm("redux.sync.max.u32 %0, %1, 0xffffffff;" : "=r"(r) : "r"(v));
    return r;
}
__device__ __forceinline__ unsigned redux_min_u32(unsigned v) {
    unsigned r;
    asm("redux.sync.min.u32 %0, %1, 0xffffffff;" : "=r"(r) : "r"(v));
    return r;
}
__device__ __forceinline__ u64 pack2(float lo, float hi) {
    return ((u64)__float_as_uint(hi) << 32) | __float_as_uint(lo);
}

// ---------------- W2 prep: reorder + transpose to quad-major ----------------
__global__ void w2prep_kernel(const float* __restrict__ W2) {
    int t = blockIdx.x * 256 + threadIdx.x;
    if (t >= 33 * C2W) return;
    int fq = t >> 8, c = t & 255;
    float v[4];
#pragma unroll
    for (int e = 0; e < 4; e++) {
        int fp = fq * 4 + e;
        float val = 0.f;
        if (fp < 131) {
            int r = (fp < 128) ? (fp + 3) : (fp - 128);
            val = W2[r * C2W + c];
        }
        v[e] = val;
    }
    g_W2q[t] = make_float4(v[0], v[1], v[2], v[3]);
}

// ---------------- FPS: 1 block/batch, points in regs, redux.sync argmax ----
__global__ void __launch_bounds__(1024, 1) fps_kernel(const float* __restrict__ x) {
    const int b = blockIdx.x;
    const float* xb = x + (size_t)b * NN * 3;
    const int t = threadIdx.x;
    const int lane = t & 31, warp = t >> 5;

    float px[8], py[8], pz[8], mind[8];
#pragma unroll
    for (int j = 0; j < 8; j++) {
        int i = t + j * 1024;
        px[j] = xb[3 * i]; py[j] = xb[3 * i + 1]; pz[j] = xb[3 * i + 2];
        mind[j] = 1e30f;
    }

    __shared__ unsigned s_val[2][32];
    __shared__ unsigned s_idx[2][32];

    if (t == 0) {
        float* sp = g_sub + (size_t)(b * MM) * 3;
        sp[0] = xb[0]; sp[1] = xb[1]; sp[2] = xb[2];
    }
    float cx = xb[0], cy = xb[1], cz = xb[2];

    for (int step = 1; step < MM; step++) {
        // update min-dist + thread-local argmax (first/lowest index kept on ties)
        float bv = -1.0f; unsigned bidx = 0;
#pragma unroll
        for (int j = 0; j < 8; j++) {
            float dx = px[j] - cx, dy = py[j] - cy, dz = pz[j] - cz;
            float d = dx * dx + dy * dy + dz * dz;
            float mj = fminf(mind[j], d);
            mind[j] = mj;
            if (mj > bv) { bv = mj; bidx = (unsigned)(t + j * 1024); }
        }
        // warp argmax: positive floats are u32-order-isomorphic
        unsigned vb = __float_as_uint(bv);
        unsigned wmax = redux_max_u32(vb);
        unsigned widx = redux_min_u32(vb == wmax ? bidx : 0xffffffffu);
        int buf = step & 1;
        if (lane == 0) { s_val[buf][warp] = wmax; s_idx[buf][warp] = widx; }
        __syncthreads();
        // block argmax: every warp redundantly reduces the 32 warp winners
        unsigned v2 = s_val[buf][lane];
        unsigned i2 = s_idx[buf][lane];
        unsigned bmax = redux_max_u32(v2);
        unsigned bix = redux_min_u32(v2 == bmax ? i2 : 0xffffffffu);

        cx = xb[3 * bix]; cy = xb[3 * bix + 1]; cz = xb[3 * bix + 2]; // broadcast LDG, L1-resident
        if (t == 0) {
            float* sp = g_sub + (size_t)(b * MM + step) * 3;
            sp[0] = cx; sp[1] = cy; sp[2] = cz;
        }
    }
}

// ---------------- KNN: 8-way split, f32x2 packed candidate pairs ------------
// Block = 256 threads = 32 queries x 8 splits; split s owns pairs p%8==s
// (candidates 2p, 2p+1). Tile stores (-2x,-2y,-2z,|s|^2) so per-pair distance'
// = w + (-2x)qx + (-2y)qy + (-2z)qz  (uniform -qq shift per query: same top-k).
#define KTS 2048
#define KPAIRS (KTS / 2)
__device__ __forceinline__ void knn_split_body(const float* __restrict__ src, int nsrc,
                                               int* __restrict__ outidx) {
    __shared__ __align__(16) float4 s_a[KPAIRS];   // (-2x0,-2x1,-2y0,-2y1)
    __shared__ __align__(16) float4 s_b[KPAIRS];   // (-2z0,-2z1, w0, w1)
    const int tid = threadIdx.x;
    const int q = tid >> 3, s = tid & 7;
    const int b = blockIdx.y;
    const int m = blockIdx.x * 32 + q;
    const bool valid = (m < MM);

    u64 qx2 = 0, qy2 = 0, qz2 = 0;
    if (valid) {
        const float* qp = g_sub + (size_t)(b * MM + m) * 3;
        qx2 = pack2(qp[0], qp[0]);
        qy2 = pack2(qp[1], qp[1]);
        qz2 = pack2(qp[2], qp[2]);
    }
    float dist[KK]; int idxr[KK];
#pragma unroll
    for (int j = 0; j < KK; j++) { dist[j] = 1e38f; idxr[j] = 0; }

    for (int base = 0; base < nsrc; base += KTS) {
        const int cntp = min(KTS, nsrc - base) >> 1;   // pair count (always even counts here)
        for (int p = tid; p < cntp; p += 256) {
            const float* sp = src + (size_t)(b * nsrc + base + 2 * p) * 3;
            float2 u = *(const float2*)sp;        // x0 y0
            float2 v = *(const float2*)(sp + 2);  // z0 x1
            float2 w = *(const float2*)(sp + 4);  // y1 z1
            float x0 = u.x, y0 = u.y, z0 = v.x, x1 = v.y, y1 = w.x, z1 = w.y;
            s_a[p] = make_float4(-2.f * x0, -2.f * x1, -2.f * y0, -2.f * y1);
            s_b[p] = make_float4(-2.f * z0, -2.f * z1,
                                 x0 * x0 + y0 * y0 + z0 * z0,
                                 x1 * x1 + y1 * y1 + z1 * z1);
        }
        __syncthreads();
        if (valid) {
#pragma unroll 4
            for (int p = s; p < cntp; p += 8) {
                ulonglong2 A = *(const ulonglong2*)&s_a[p];   // x-pair, y-pair
                ulonglong2 Bv = *(const ulonglong2*)&s_b[p];  // z-pair, w-pair
                u64 acc = ffma2(Bv.x, qz2, Bv.y);
                acc = ffma2(A.y, qy2, acc);
                acc = ffma2(A.x, qx2, acc);
                float d0 = __uint_as_float((unsigned)(acc & 0xffffffffu));
                float d1 = __uint_as_float((unsigned)(acc >> 32));
                int cbase = base + 2 * p;
                if (d0 < dist[KK - 1]) {
                    dist[KK - 1] = d0; idxr[KK - 1] = cbase;
#pragma unroll
                    for (int r = KK - 1; r > 0; --r) {
                        if (dist[r] < dist[r - 1]) {
                            float td = dist[r]; dist[r] = dist[r - 1]; dist[r - 1] = td;
                            int ti = idxr[r]; idxr[r] = idxr[r - 1]; idxr[r - 1] = ti;
                        }
                    }
                }
                if (d1 < dist[KK - 1]) {
                    dist[KK - 1] = d1; idxr[KK - 1] = cbase + 1;
#pragma unroll
                    for (int r = KK - 1; r > 0; --r) {
                        if (dist[r] < dist[r - 1]) {
                            float td = dist[r]; dist[r] = dist[r - 1]; dist[r - 1] = td;
                            int ti = idxr[r]; idxr[r] = idxr[r - 1]; idxr[r - 1] = ti;
                        }
                    }
                }
            }
        }
        __syncthreads();   // tile reuse (and list completion before merge reuse)
    }

    // ---- merge: smem reuse, [r][256] conflict-free ----
    float* md = (float*)s_a;   // 16KB = 16*256 floats
    int*   mi = (int*)s_b;     // 16KB
#pragma unroll
    for (int r = 0; r < KK; r++) {
        md[r * 256 + tid] = dist[r];
        mi[r * 256 + tid] = idxr[r];
    }
    __syncthreads();

    if (tid < 32) {
        int mq = blockIdx.x * 32 + tid;
        if (mq < MM) {
            int p[8] = {0, 0, 0, 0, 0, 0, 0, 0};
            int* op = outidx + (size_t)(b * MM + mq) * KK;
#pragma unroll 1
            for (int r = 0; r < KK; r++) {
                float bd = 3e38f; int bi = 0x7fffffff; int bs = 0;
#pragma unroll
                for (int ss = 0; ss < 8; ss++) {
                    int ps = p[ss];
                    if (ps < KK) {
                        float d = md[ps * 256 + tid * 8 + ss];
                        int   ii = mi[ps * 256 + tid * 8 + ss];
                        if (d < bd || (d == bd && ii < bi)) { bd = d; bi = ii; bs = ss; }
                    }
                }
                p[bs]++;
                op[r] = bi;
            }
        }
    }
}

__global__ void __launch_bounds__(256) knn1_kernel(const float* __restrict__ x) {
    knn_split_body(x, NN, g_idx1);
}
__global__ void __launch_bounds__(256) knn2_kernel() {
    knn_split_body(g_sub, MM, g_idx2);
}

// ---------------- Layer 1: warp per query, 4 channels per lane -------------
__global__ void __launch_bounds__(128) layer1_kernel(const float* __restrict__ x,
                                                     const float* __restrict__ W1,
                                                     const float* __restrict__ b1) {
    __shared__ float sW[6 * C1W];
    int tid = threadIdx.x;
    for (int i = tid; i < 6 * C1W; i += 128) sW[i] = W1[i];
    __syncthreads();

    int warp = tid >> 5, lane = tid & 31;
    int b = blockIdx.y;
    int m = blockIdx.x * 4 + warp;

    const float* cp = g_sub + (size_t)(b * MM + m) * 3;
    float cx = cp[0], cy = cp[1], cz = cp[2];
    int c0 = lane * 4;
    float bb[4] = { b1[c0], b1[c0 + 1], b1[c0 + 2], b1[c0 + 3] };
    float best[4] = { 0.f, 0.f, 0.f, 0.f };
    const int* ip = g_idx1 + (size_t)(b * MM + m) * KK;

#pragma unroll 1
    for (int k = 0; k < KK; k++) {
        int n = ip[k];
        const float* np = x + ((size_t)b * NN + n) * 3;
        float nx = np[0], ny = np[1], nz = np[2];
        float f[6]; f[0] = nx - cx; f[1] = ny - cy; f[2] = nz - cz; f[3] = nx; f[4] = ny; f[5] = nz;
        float a[4] = { bb[0], bb[1], bb[2], bb[3] };
#pragma unroll
        for (int ff = 0; ff < 6; ff++) {
            const float* w = sW + ff * C1W + c0;
            a[0] += f[ff] * w[0]; a[1] += f[ff] * w[1];
            a[2] += f[ff] * w[2]; a[3] += f[ff] * w[3];
        }
#pragma unroll
        for (int e = 0; e < 4; e++) best[e] = fmaxf(best[e], fmaxf(a[e], 0.f));
    }
    *(float4*)(g_f1 + ((size_t)(b * MM + m) * C1W + c0)) =
        make_float4(best[0], best[1], best[2], best[3]);
}

// ---------------- Layer 2: 256 threads = channels, 4 queries, FFMA2 --------
#define CH 4
__global__ void __launch_bounds__(256, 1) layer2_kernel(const float* __restrict__ b2) {
    __shared__ __align__(16) float sfeat[CH * 16 * 132];
    __shared__ int s_n[CH * 16];

    int b = blockIdx.y, m0 = blockIdx.x * CH;
    int tid = threadIdx.x;

    if (tid < CH * 16) {
        int mm = tid >> 4, k = tid & 15;
        int m = m0 + mm;
        int n = g_idx2[(size_t)(b * MM + m) * KK + k];
        s_n[tid] = n;
        const float* cp = g_sub + (size_t)(b * MM + m) * 3;
        const float* np = g_sub + (size_t)(b * MM + n) * 3;
        float* row = sfeat + tid * 132;
        row[128] = np[0] - cp[0];
        row[129] = np[1] - cp[1];
        row[130] = np[2] - cp[2];
        row[131] = 0.f;
    }
    __syncthreads();
    for (int t = tid; t < CH * 16 * 32; t += 256) {
        int p = t >> 5, fq = t & 31;
        int n = s_n[p];
        float4 v = *(const float4*)(g_f1 + (size_t)(b * MM + n) * C1W + fq * 4);
        *(float4*)(sfeat + p * 132 + fq * 4) = v;
    }
    int c = tid;
    u64 wpk[66];
#pragma unroll
    for (int qd = 0; qd < 33; qd++) {
        float4 w = g_W2q[qd * C2W + c];
        wpk[2 * qd]     = pack2(w.x, w.y);
        wpk[2 * qd + 1] = pack2(w.z, w.w);
    }
    u64 bias = (u64)__float_as_uint(b2[c]);   // lo = bias, hi = 0
    __syncthreads();

    float best[CH];
#pragma unroll
    for (int mm = 0; mm < CH; mm++) best[mm] = 0.f;

#pragma unroll 1
    for (int k = 0; k < 16; k++) {
        u64 acc[CH];
#pragma unroll
        for (int mm = 0; mm < CH; mm++) acc[mm] = bias;
#pragma unroll
        for (int q2 = 0; q2 < 33; q2++) {
#pragma unroll
            for (int mm = 0; mm < CH; mm++) {
                const ulonglong2* vrow = (const ulonglong2*)(sfeat + (mm * 16 + k) * 132);
                ulonglong2 v = vrow[q2];
                acc[mm] = ffma2(v.x, wpk[2 * q2], acc[mm]);
                acc[mm] = ffma2(v.y, wpk[2 * q2 + 1], acc[mm]);
            }
        }
#pragma unroll
        for (int mm = 0; mm < CH; mm++) {
            float lo = __uint_as_float((unsigned)(acc[mm] & 0xffffffffu));
            float hi = __uint_as_float((unsigned)(acc[mm] >> 32));
            float a = lo + hi;
            best[mm] = fmaxf(best[mm], fmaxf(a, 0.f));
        }
    }
#pragma unroll
    for (int mm = 0; mm < CH; mm++)
        g_f2[(size_t)(b * MM + m0 + mm) * C2W + c] = best[mm];
}

// ---------------- fused adaptive max+avg pool ------------------------------
__global__ void __launch_bounds__(256) pool_kernel(float* __restrict__ out) {
    int c = threadIdx.x;
    int o = blockIdx.x;
    int b = blockIdx.y;
    const float* f = g_f2 + ((size_t)(b * MM + o * 20) * C2W) + c;
    float mx = -1e38f, sm = 0.f;
#pragma unroll
    for (int w = 0; w < 20; w++) {
        float v = f[(size_t)w * C2W];
        mx = fmaxf(mx, v);
        sm += v;
    }
    out[((size_t)b * C2W + c) * NOUT + o] = mx + sm / 20.0f;
}

// ---------------- launch ----------------------------------------------------
extern "C" void kernel_launch(void* const* d_in, const int* in_sizes, int n_in,
                              void* d_out, int out_size) {
    const float* x  = (const float*)d_in[0];
    const float* W1 = (const float*)d_in[1];
    const float* b1 = (const float*)d_in[2];
    const float* W2 = (const float*)d_in[3];
    const float* b2 = (const float*)d_in[4];
    float* out = (float*)d_out;

    w2prep_kernel<<<33, 256>>>(W2);
    fps_kernel<<<BB, 1024>>>(x);
    knn1_kernel<<<dim3((MM + 31) / 32, BB), 256>>>(x);
    knn2_kernel<<<dim3((MM + 31) / 32, BB), 256>>>();
    layer1_kernel<<<dim3(MM / 4, BB), 128>>>(x, W1, b1);
    layer2_kernel<<<dim3(MM / CH, BB), 256>>>(b2);
    pool_kernel<<<dim3(NOUT, BB), 256>>>(out);
}